// round 3
// baseline (speedup 1.0000x reference)
#include <cuda_runtime.h>
#include <cuda_bf16.h>
#include <math.h>

// ---------------------------------------------------------------------------
// SMPL LBS point deformer.
// Inputs (metadata order):
//  0 points      (3, N)        float32
//  1 weights     (24, N)       float32
//  2 beta        (10,)         float32
//  3 theta       (24, 3)       float32
//  4 da_theta    (24, 3)       float32
//  5 shapedirs   (NV, 3, 10)   float32
//  6 v_template  (NV, 3)       float32
//  7 J_regressor (24, NV)      float32
// Output: (1, 3, N) float32
// ---------------------------------------------------------------------------

#define NJ 24
#define NV_MAX 8192

__constant__ int c_par[NJ] = {-1,0,0,0,1,2,3,4,5,6,7,8,9,9,9,12,13,14,16,17,18,19,20,21};

__device__ float g_vshaped[NV_MAX * 3];
__device__ float g_J[2][NJ * 3];      // [0]=pose (shaped), [1]=da (template)
__device__ float g_A[NJ * 12];        // row-major 3x4 per joint

// ---------------------------------------------------------------------------
// Kernel 0: v_shaped = v_template + shapedirs @ beta   (NV*3 elements)
// ---------------------------------------------------------------------------
__global__ void k_vshape(const float* __restrict__ shapedirs,
                         const float* __restrict__ v_template,
                         const float* __restrict__ beta, int nv3) {
    int i = blockIdx.x * blockDim.x + threadIdx.x;
    if (i >= nv3) return;
    const float* sd = shapedirs + (size_t)i * 10;
    float s = v_template[i];
#pragma unroll
    for (int k = 0; k < 10; k++) s += sd[k] * __ldg(&beta[k]);
    g_vshaped[i] = s;
}

// ---------------------------------------------------------------------------
// Kernel 1: J[j] = J_regressor[j] @ v_shaped  (and @ v_template for 'da')
// One block per joint, 256-thread block reduction.
// ---------------------------------------------------------------------------
__global__ void k_joints(const float* __restrict__ Jreg,
                         const float* __restrict__ v_template, int nv) {
    int j = blockIdx.x;
    const float* r = Jreg + (size_t)j * nv;
    float p0 = 0.f, p1 = 0.f, p2 = 0.f;   // pose (shaped)
    float d0 = 0.f, d1 = 0.f, d2 = 0.f;   // da (template)
    for (int v = threadIdx.x; v < nv; v += blockDim.x) {
        float w = r[v];
        d0 += w * v_template[v * 3 + 0];
        d1 += w * v_template[v * 3 + 1];
        d2 += w * v_template[v * 3 + 2];
        p0 += w * g_vshaped[v * 3 + 0];
        p1 += w * g_vshaped[v * 3 + 1];
        p2 += w * g_vshaped[v * 3 + 2];
    }
#pragma unroll
    for (int off = 16; off > 0; off >>= 1) {
        p0 += __shfl_down_sync(0xffffffffu, p0, off);
        p1 += __shfl_down_sync(0xffffffffu, p1, off);
        p2 += __shfl_down_sync(0xffffffffu, p2, off);
        d0 += __shfl_down_sync(0xffffffffu, d0, off);
        d1 += __shfl_down_sync(0xffffffffu, d1, off);
        d2 += __shfl_down_sync(0xffffffffu, d2, off);
    }
    __shared__ float red[8][6];
    int lane = threadIdx.x & 31, warp = threadIdx.x >> 5;
    if (lane == 0) {
        red[warp][0] = p0; red[warp][1] = p1; red[warp][2] = p2;
        red[warp][3] = d0; red[warp][4] = d1; red[warp][5] = d2;
    }
    __syncthreads();
    if (threadIdx.x == 0) {
        float s[6] = {0, 0, 0, 0, 0, 0};
        int nw = (blockDim.x + 31) >> 5;
        for (int w = 0; w < nw; w++)
            for (int k = 0; k < 6; k++) s[k] += red[w][k];
        g_J[0][j * 3 + 0] = s[0]; g_J[0][j * 3 + 1] = s[1]; g_J[0][j * 3 + 2] = s[2];
        g_J[1][j * 3 + 0] = s[3]; g_J[1][j * 3 + 1] = s[4]; g_J[1][j * 3 + 2] = s[5];
    }
}

// ---------------------------------------------------------------------------
// Kernel 2: Rodrigues + kinematic chain + pack + A = pose * inv(da)
// Single 64-thread block. Layout per transform: R[9] (row-major), t[3].
// ---------------------------------------------------------------------------
__global__ void k_transforms(const float* __restrict__ theta,
                             const float* __restrict__ da_theta) {
    __shared__ float L[2][NJ][12];
    __shared__ float G[2][NJ][12];
    int t = threadIdx.x;

    if (t < 48) {
        int s = t / NJ;          // 0 = pose, 1 = da
        int j = t % NJ;
        const float* th = (s == 0 ? theta : da_theta) + j * 3;
        float rx = th[0], ry = th[1], rz = th[2];
        float nrm = sqrtf(rx * rx + ry * ry + rz * rz) + 1e-8f;
        float x = rx / nrm, y = ry / nrm, z = rz / nrm;
        float c = cosf(nrm), sn = sinf(nrm), ic = 1.0f - c;
        float* Lj = L[s][j];
        Lj[0] = c + ic * x * x;      Lj[1] = ic * x * y - sn * z;  Lj[2] = ic * x * z + sn * y;
        Lj[3] = ic * x * y + sn * z; Lj[4] = c + ic * y * y;       Lj[5] = ic * y * z - sn * x;
        Lj[6] = ic * x * z - sn * y; Lj[7] = ic * y * z + sn * x;  Lj[8] = c + ic * z * z;
        const float* J = g_J[s];
        int p = c_par[j];
        if (p < 0) {
            Lj[9] = J[0]; Lj[10] = J[1]; Lj[11] = J[2];
        } else {
            Lj[9]  = J[j * 3 + 0] - J[p * 3 + 0];
            Lj[10] = J[j * 3 + 1] - J[p * 3 + 1];
            Lj[11] = J[j * 3 + 2] - J[p * 3 + 2];
        }
    }
    __syncthreads();

    if (t < 2) {
        int s = t;
        for (int k = 0; k < 12; k++) G[s][0][k] = L[s][0][k];
        for (int j = 1; j < NJ; j++) {
            int p = c_par[j];
            const float* Gp = G[s][p];
            const float* Lj = L[s][j];
            float* Gj = G[s][j];
            for (int r = 0; r < 3; r++) {
                for (int c = 0; c < 3; c++)
                    Gj[r * 3 + c] = Gp[r * 3 + 0] * Lj[0 * 3 + c] +
                                    Gp[r * 3 + 1] * Lj[1 * 3 + c] +
                                    Gp[r * 3 + 2] * Lj[2 * 3 + c];
                Gj[9 + r] = Gp[r * 3 + 0] * Lj[9] + Gp[r * 3 + 1] * Lj[10] +
                            Gp[r * 3 + 2] * Lj[11] + Gp[9 + r];
            }
        }
        // pack: t -= R @ J_rest[j]
        for (int j = 0; j < NJ; j++) {
            const float* J = &g_J[s][j * 3];
            float* Gj = G[s][j];
            for (int r = 0; r < 3; r++)
                Gj[9 + r] -= Gj[r * 3 + 0] * J[0] + Gj[r * 3 + 1] * J[1] + Gj[r * 3 + 2] * J[2];
        }
    }
    __syncthreads();

    if (t < NJ) {
        int j = t;
        const float* P = G[0][j];   // pose
        const float* D = G[1][j];   // da (rigid: R orthogonal)
        // A.R[r][c] = sum_k Rp[r][k] * Rd[c][k]   (Rd^T)
        float AR[9];
        for (int r = 0; r < 3; r++)
            for (int c = 0; c < 3; c++)
                AR[r * 3 + c] = P[r * 3 + 0] * D[c * 3 + 0] +
                                P[r * 3 + 1] * D[c * 3 + 1] +
                                P[r * 3 + 2] * D[c * 3 + 2];
        // t' = -Rd^T td ;  A.t = Rp @ t' + tp
        float ti[3];
        for (int r = 0; r < 3; r++)
            ti[r] = -(D[0 * 3 + r] * D[9] + D[1 * 3 + r] * D[10] + D[2 * 3 + r] * D[11]);
        for (int r = 0; r < 3; r++) {
            float at = P[r * 3 + 0] * ti[0] + P[r * 3 + 1] * ti[1] +
                       P[r * 3 + 2] * ti[2] + P[9 + r];
            g_A[j * 12 + r * 4 + 0] = AR[r * 3 + 0];
            g_A[j * 12 + r * 4 + 1] = AR[r * 3 + 1];
            g_A[j * 12 + r * 4 + 2] = AR[r * 3 + 2];
            g_A[j * 12 + r * 4 + 3] = at;
        }
    }
}

// ---------------------------------------------------------------------------
// Kernel 3: the heavy per-point pass, packed f32x2 math.
// Each thread handles 4 points (two f32x2 pairs) with 16B vector loads.
// ---------------------------------------------------------------------------
__device__ __forceinline__ unsigned long long fma2(unsigned long long a,
                                                   unsigned long long b,
                                                   unsigned long long c) {
    unsigned long long d;
    asm("fma.rn.f32x2 %0, %1, %2, %3;" : "=l"(d) : "l"(a), "l"(b), "l"(c));
    return d;
}

__global__ void __launch_bounds__(256) k_lbs_vec(
    const float* __restrict__ points, const float* __restrict__ weights,
    float* __restrict__ out, int N, long long nGroups) {
    __shared__ unsigned long long sA[NJ * 12];   // each entry = {a, a} packed
    for (int i = threadIdx.x; i < NJ * 12; i += blockDim.x) {
        unsigned long long u = (unsigned long long)__float_as_uint(g_A[i]);
        sA[i] = u | (u << 32);
    }
    __syncthreads();

    long long g = (long long)blockIdx.x * blockDim.x + threadIdx.x;
    if (g >= nGroups) return;

    const ulonglong2 X = reinterpret_cast<const ulonglong2*>(points)[g];
    const ulonglong2 Y = reinterpret_cast<const ulonglong2*>(points + (size_t)N)[g];
    const ulonglong2 Z = reinterpret_cast<const ulonglong2*>(points + 2 * (size_t)N)[g];

    unsigned long long vxa = 0ull, vya = 0ull, vza = 0ull;
    unsigned long long vxb = 0ull, vyb = 0ull, vzb = 0ull;

#pragma unroll
    for (int j = 0; j < NJ; j++) {
        const ulonglong2 W =
            reinterpret_cast<const ulonglong2*>(weights + (size_t)j * N)[g];
        const unsigned long long* a = &sA[j * 12];
        unsigned long long s;
        // pair a (points 4g, 4g+1)
        s = fma2(a[0], X.x, a[3]);  s = fma2(a[1], Y.x, s);  s = fma2(a[2],  Z.x, s);  vxa = fma2(W.x, s, vxa);
        s = fma2(a[4], X.x, a[7]);  s = fma2(a[5], Y.x, s);  s = fma2(a[6],  Z.x, s);  vya = fma2(W.x, s, vya);
        s = fma2(a[8], X.x, a[11]); s = fma2(a[9], Y.x, s);  s = fma2(a[10], Z.x, s);  vza = fma2(W.x, s, vza);
        // pair b (points 4g+2, 4g+3)
        s = fma2(a[0], X.y, a[3]);  s = fma2(a[1], Y.y, s);  s = fma2(a[2],  Z.y, s);  vxb = fma2(W.y, s, vxb);
        s = fma2(a[4], X.y, a[7]);  s = fma2(a[5], Y.y, s);  s = fma2(a[6],  Z.y, s);  vyb = fma2(W.y, s, vyb);
        s = fma2(a[8], X.y, a[11]); s = fma2(a[9], Y.y, s);  s = fma2(a[10], Z.y, s);  vzb = fma2(W.y, s, vzb);
    }

    ulonglong2 o;
    o.x = vxa; o.y = vxb; reinterpret_cast<ulonglong2*>(out)[g] = o;
    o.x = vya; o.y = vyb; reinterpret_cast<ulonglong2*>(out + (size_t)N)[g] = o;
    o.x = vza; o.y = vzb; reinterpret_cast<ulonglong2*>(out + 2 * (size_t)N)[g] = o;
}

// Scalar fallback (only used if N % 4 != 0 — not the case for this problem).
__global__ void k_lbs_scalar(const float* __restrict__ points,
                             const float* __restrict__ weights,
                             float* __restrict__ out, int N) {
    __shared__ float sA[NJ * 12];
    for (int i = threadIdx.x; i < NJ * 12; i += blockDim.x) sA[i] = g_A[i];
    __syncthreads();
    long long n = (long long)blockIdx.x * blockDim.x + threadIdx.x;
    if (n >= N) return;
    float px = points[n], py = points[(size_t)N + n], pz = points[2 * (size_t)N + n];
    float vx = 0.f, vy = 0.f, vz = 0.f;
#pragma unroll
    for (int j = 0; j < NJ; j++) {
        float w = weights[(size_t)j * N + n];
        const float* a = &sA[j * 12];
        vx += w * (a[0] * px + a[1] * py + a[2]  * pz + a[3]);
        vy += w * (a[4] * px + a[5] * py + a[6]  * pz + a[7]);
        vz += w * (a[8] * px + a[9] * py + a[10] * pz + a[11]);
    }
    out[n] = vx; out[(size_t)N + n] = vy; out[2 * (size_t)N + n] = vz;
}

// ---------------------------------------------------------------------------
extern "C" void kernel_launch(void* const* d_in, const int* in_sizes, int n_in,
                              void* d_out, int out_size) {
    const float* points      = (const float*)d_in[0];
    const float* weights     = (const float*)d_in[1];
    const float* beta        = (const float*)d_in[2];
    const float* theta       = (const float*)d_in[3];
    const float* da_theta    = (const float*)d_in[4];
    const float* shapedirs   = (const float*)d_in[5];
    const float* v_template  = (const float*)d_in[6];
    const float* J_regressor = (const float*)d_in[7];

    int N  = in_sizes[0] / 3;          // number of points
    int NV = in_sizes[5] / 30;         // template vertex count
    int nv3 = NV * 3;

    // prep
    k_vshape<<<(nv3 + 255) / 256, 256>>>(shapedirs, v_template, beta, nv3);
    k_joints<<<NJ, 256>>>(J_regressor, v_template, NV);
    k_transforms<<<1, 64>>>(theta, da_theta);

    // main pass
    if ((N & 3) == 0) {
        long long nGroups = (long long)N / 4;
        int blocks = (int)((nGroups + 255) / 256);
        k_lbs_vec<<<blocks, 256>>>(points, weights, (float*)d_out, N, nGroups);
    } else {
        int blocks = (N + 255) / 256;
        k_lbs_scalar<<<blocks, 256>>>(points, weights, (float*)d_out, N);
    }
}